// round 13
// baseline (speedup 1.0000x reference)
#include <cuda_runtime.h>
#include <cuda_fp16.h>
#include <cstdint>
#include <math.h>

// ---------------------------------------------------------------------------
// SingleHeadAttention B=4, T=2048, C=1024 fp32 — fp16 2-term mma.sync GEMMs
//   hi term: f32-accum HMMA (half rate);  lo term: f16-accum HMMA (full rate)
//   lo operands pre-scaled x1024 (mid-range f16, no subnormals); /1024 at epi.
//   qkv = x @ w^T   (fused epilogue -> qh/ql fp16, kh fp16, v fp32)
//   S   = q k^T/32  (causal tile-skip) -> att fp32
//   P   = softmax   -> fp16 hi/lo(x1024)
//   y   = P @ (V^T)^T (causal K-limit)
// R12: R11 skeleton (CTA 128x128, 256 thr, 8 warps 2m x 4n, kc=32, 3-stage,
//      1 CTA/SM, fragment double buffering).
// ---------------------------------------------------------------------------

#define LO_SCALE 1024.0f
#define LO_INV   (1.0f / 1024.0f)

// ------------------------------ scratch ------------------------------------
__device__ float g_att[(size_t)4 * 2048 * 2048];
__device__ float g_vf[(size_t)4 * 2048 * 1024];
__device__ __half g_xh[(size_t)8192 * 1024];
__device__ __half g_xl[(size_t)8192 * 1024];          // x1024
__device__ __half g_wh[(size_t)3072 * 1024];
__device__ __half g_qh[(size_t)4 * 2048 * 1024];
__device__ __half g_ql[(size_t)4 * 2048 * 1024];      // x1024
__device__ __half g_kh[(size_t)4 * 2048 * 1024];
__device__ __half g_vth[(size_t)4 * 1024 * 2048];     // V^T
__device__ __half g_ph[(size_t)4 * 2048 * 2048];
__device__ __half g_pl[(size_t)4 * 2048 * 2048];      // x1024

// ------------------------------ helpers ------------------------------------
#define SA 40                                 // padded smem row stride (halfs)
#define TILE_B (128 * SA * 2)                 // 10240 per operand tile
#define STAGE_B (3 * TILE_B)                  // Ah, Al, Bh = 30720
#define GEMM_SMEM (3 * STAGE_B)               // 92160 -> 1 CTA/SM
#define KOFF16 32

__device__ __forceinline__ uint32_t smem_u32(const void* p) {
    uint32_t a;
    asm("{ .reg .u64 t; cvta.to.shared.u64 t, %1; cvt.u32.u64 %0, t; }" : "=r"(a) : "l"(p));
    return a;
}
__device__ __forceinline__ void cp16(uint32_t dst, const void* src) {
    asm volatile("cp.async.cg.shared.global [%0], [%1], 16;" :: "r"(dst), "l"(src));
}
__device__ __forceinline__ void ldmx4(uint32_t* r, uint32_t addr) {
    asm volatile("ldmatrix.sync.aligned.m8n8.x4.shared.b16 {%0,%1,%2,%3}, [%4];"
                 : "=r"(r[0]), "=r"(r[1]), "=r"(r[2]), "=r"(r[3]) : "r"(addr));
}
// hi term: f32 accumulate
__device__ __forceinline__ void mma_f32(float* c, const uint32_t* a, const uint32_t* b) {
    asm volatile(
        "mma.sync.aligned.m16n8k16.row.col.f32.f16.f16.f32 "
        "{%0,%1,%2,%3}, {%4,%5,%6,%7}, {%8,%9}, {%0,%1,%2,%3};"
        : "+f"(c[0]), "+f"(c[1]), "+f"(c[2]), "+f"(c[3])
        : "r"(a[0]), "r"(a[1]), "r"(a[2]), "r"(a[3]), "r"(b[0]), "r"(b[1]));
}
// lo term: f16 accumulate (2 b32 regs of half2)
__device__ __forceinline__ void mma_f16(uint32_t* c, const uint32_t* a, const uint32_t* b) {
    asm volatile(
        "mma.sync.aligned.m16n8k16.row.col.f16.f16.f16.f16 "
        "{%0,%1}, {%2,%3,%4,%5}, {%6,%7}, {%0,%1};"
        : "+r"(c[0]), "+r"(c[1])
        : "r"(a[0]), "r"(a[1]), "r"(a[2]), "r"(a[3]), "r"(b[0]), "r"(b[1]));
}
__device__ __forceinline__ uint32_t pack2h(float v0, float v1) {
    __half2 h = __floats2half2_rn(v0, v1);
    return *(uint32_t*)&h;
}

// ------------------------------ GEMM ---------------------------------------
// mode 0: C = alpha * (hi + lo/1024);  mode 1: fused qkv split epilogue
__global__ __launch_bounds__(256, 1)
void gemm2_kernel(const __half* __restrict__ Ah, const __half* __restrict__ Al,
                  const __half* __restrict__ Bh,
                  float* __restrict__ C,
                  int K, int lda, int ldb, int ldc,
                  long long sAo, long long sBo, long long sCo,
                  float alpha, int causal_skip, int causal_klim, int mode, int rev_y)
{
    const int by = rev_y ? (gridDim.y - 1 - blockIdx.y) : blockIdx.y;
    const int m0 = by * 128;
    const int n0 = blockIdx.x * 128;
    if (causal_skip && n0 > m0 + 127) return;

    const int bz = blockIdx.z;
    Ah += (long long)bz * sAo;  Al += (long long)bz * sAo;
    Bh += (long long)bz * sBo;
    C  += (long long)bz * sCo;

    int Keff = K;
    if (causal_klim) { int lim = m0 + 128; Keff = (lim < K) ? lim : K; }
    const int NC = Keff / 32;

    extern __shared__ char smem[];
    const uint32_t sb = smem_u32(smem);
    const int tid = threadIdx.x;
    const int wid = tid >> 5;
    const int lane = tid & 31;

    auto load_stage = [&](int s, int c) {
        const uint32_t base = sb + s * STAGE_B;
        const int k0 = c * 32;
#pragma unroll
        for (int it = 0; it < 2; ++it) {
            const int id  = tid + it * 256;
            const int row = id >> 2;
            const int c16 = id & 3;
            const uint32_t so = (uint32_t)(row * SA + c16 * 8) * 2;
            const long long ga = (long long)(m0 + row) * lda + k0 + c16 * 8;
            const long long gb = (long long)(n0 + row) * ldb + k0 + c16 * 8;
            cp16(base + so,              Ah + ga);
            cp16(base + TILE_B + so,     Al + ga);
            cp16(base + 2 * TILE_B + so, Bh + gb);
        }
        asm volatile("cp.async.commit_group;" ::: "memory");
    };

    float acc[4][4][4];
    uint32_t accl[4][4][2];
#pragma unroll
    for (int i = 0; i < 4; ++i)
#pragma unroll
        for (int j = 0; j < 4; ++j) {
#pragma unroll
            for (int q = 0; q < 4; ++q) acc[i][j][q] = 0.f;
            accl[i][j][0] = 0u; accl[i][j][1] = 0u;
        }

    const int wm = (wid & 1) * 64;
    const int wn = (wid >> 1) * 32;
    const int gr = lane >> 3;
    const int rr = lane & 7;

    const uint32_t a_off = (uint32_t)((wm + (gr & 1) * 8 + rr) * SA + (gr >> 1) * 8) * 2;
    const uint32_t b_off = (uint32_t)((wn + (gr >> 1) * 8 + rr) * SA + (gr & 1) * 8) * 2;

    uint32_t fah0[4][4], fal0[4][4], fbh0[4][2];
    uint32_t fah1[4][4], fal1[4][4], fbh1[4][2];

    auto load_frags = [&](uint32_t st, uint32_t koff,
                          uint32_t (&fah)[4][4], uint32_t (&fal)[4][4],
                          uint32_t (&fbh)[4][2]) {
#pragma unroll
        for (int nt = 0; nt < 2; ++nt) {
            uint32_t r[4];
            ldmx4(r, st + 2 * TILE_B + b_off + koff + (uint32_t)(nt * 16 * SA) * 2);
            fbh[nt * 2 + 0][0] = r[0]; fbh[nt * 2 + 0][1] = r[1];
            fbh[nt * 2 + 1][0] = r[2]; fbh[nt * 2 + 1][1] = r[3];
        }
#pragma unroll
        for (int mi = 0; mi < 4; ++mi) {
            const uint32_t off = a_off + koff + (uint32_t)(mi * 16 * SA) * 2;
            ldmx4(fah[mi], st + off);
            ldmx4(fal[mi], st + TILE_B + off);
        }
    };
    auto mma_all = [&](uint32_t (&fah)[4][4], uint32_t (&fal)[4][4],
                       uint32_t (&fbh)[4][2]) {
#pragma unroll
        for (int mi = 0; mi < 4; ++mi) {
#pragma unroll
            for (int nj = 0; nj < 4; ++nj) mma_f32(acc[mi][nj], fah[mi], fbh[nj]);
#pragma unroll
            for (int nj = 0; nj < 4; ++nj) mma_f16(accl[mi][nj], fal[mi], fbh[nj]);
        }
    };

    load_stage(0, 0);
    load_stage(1, 1);
    load_stage(2, 2);
    asm volatile("cp.async.wait_group 2;" ::: "memory");
    __syncthreads();
    load_frags(sb, 0, fah0, fal0, fbh0);

    for (int c = 0; c < NC; ++c) {
        const uint32_t st = sb + (c % 3) * STAGE_B;

        load_frags(st, KOFF16, fah1, fal1, fbh1);
        mma_all(fah0, fal0, fbh0);

        if (c + 2 < NC) asm volatile("cp.async.wait_group 1;" ::: "memory");
        else            asm volatile("cp.async.wait_group 0;" ::: "memory");
        __syncthreads();
        if (c + 3 < NC) load_stage(c % 3, c + 3);
        if (c + 1 < NC)
            load_frags(sb + ((c + 1) % 3) * STAGE_B, 0, fah0, fal0, fbh0);

        mma_all(fah1, fal1, fbh1);
    }

    // ---- epilogue: combine hi + lo/1024 ----
#pragma unroll
    for (int mi = 0; mi < 4; ++mi)
#pragma unroll
        for (int nj = 0; nj < 4; ++nj) {
            __half2 l0 = *(__half2*)&accl[mi][nj][0];
            __half2 l1 = *(__half2*)&accl[mi][nj][1];
            acc[mi][nj][0] += LO_INV * __half2float(l0.x);
            acc[mi][nj][1] += LO_INV * __half2float(l0.y);
            acc[mi][nj][2] += LO_INV * __half2float(l1.x);
            acc[mi][nj][3] += LO_INV * __half2float(l1.y);
        }

    if (mode == 0) {
#pragma unroll
        for (int mi = 0; mi < 4; ++mi)
#pragma unroll
            for (int nj = 0; nj < 4; ++nj) {
                const int row = m0 + wm + mi * 16 + (lane >> 2);
                const int col = n0 + wn + nj * 8 + (lane & 3) * 2;
                float2 v0 = make_float2(alpha * acc[mi][nj][0], alpha * acc[mi][nj][1]);
                float2 v1 = make_float2(alpha * acc[mi][nj][2], alpha * acc[mi][nj][3]);
                *(float2*)(C + (long long)row * ldc + col)       = v0;
                *(float2*)(C + (long long)(row + 8) * ldc + col) = v1;
            }
    } else {
        const int seg = n0 >> 10;                      // 0=q 1=k 2=v
#pragma unroll
        for (int mi = 0; mi < 4; ++mi)
#pragma unroll
            for (int nj = 0; nj < 4; ++nj) {
                const int row = m0 + wm + mi * 16 + (lane >> 2);
                const int cc  = (n0 & 1023) + wn + nj * 8 + (lane & 3) * 2;
                const float v00 = acc[mi][nj][0], v01 = acc[mi][nj][1];
                const float v10 = acc[mi][nj][2], v11 = acc[mi][nj][3];
                const long long o0 = (long long)row * 1024 + cc;
                const long long o1 = (long long)(row + 8) * 1024 + cc;
                if (seg == 2) {
                    *(float2*)(g_vf + o0) = make_float2(v00, v01);
                    *(float2*)(g_vf + o1) = make_float2(v10, v11);
                } else if (seg == 1) {                 // k: single fp16
                    *(uint32_t*)(g_kh + o0) = pack2h(v00, v01);
                    *(uint32_t*)(g_kh + o1) = pack2h(v10, v11);
                } else {                               // q: fp16 hi + lo(x1024)
                    __half h00 = __float2half_rn(v00), h01 = __float2half_rn(v01);
                    __half h10 = __float2half_rn(v10), h11 = __float2half_rn(v11);
                    __half2 p0; p0.x = h00; p0.y = h01;
                    __half2 p1; p1.x = h10; p1.y = h11;
                    *(uint32_t*)(g_qh + o0) = *(uint32_t*)&p0;
                    *(uint32_t*)(g_qh + o1) = *(uint32_t*)&p1;
                    *(uint32_t*)(g_ql + o0) = pack2h((v00 - __half2float(h00)) * LO_SCALE,
                                                     (v01 - __half2float(h01)) * LO_SCALE);
                    *(uint32_t*)(g_ql + o1) = pack2h((v10 - __half2float(h10)) * LO_SCALE,
                                                     (v11 - __half2float(h11)) * LO_SCALE);
                }
            }
    }
}

// --------------------- merged input split (x hi/lo, w single) --------------
#define X_N4 (8192LL * 1024 / 4)
#define W_N4 (3072LL * 1024 / 4)
__global__ void split_xw_kernel(const float* __restrict__ x, const float* __restrict__ w,
                                __half* __restrict__ xh, __half* __restrict__ xl,
                                __half* __restrict__ wh)
{
    long long i = (long long)blockIdx.x * blockDim.x + threadIdx.x;
    if (i < X_N4) {
        float4 v = *(const float4*)(x + i * 4);
        __half hv[4], lv[4];
#pragma unroll
        for (int q = 0; q < 4; ++q) {
            float f = (&v.x)[q];
            hv[q] = __float2half_rn(f);
            lv[q] = __float2half_rn((f - __half2float(hv[q])) * LO_SCALE);
        }
        *(uint2*)(xh + i * 4) = *(uint2*)hv;
        *(uint2*)(xl + i * 4) = *(uint2*)lv;
    } else {
        long long o = i - X_N4;
        if (o >= W_N4) return;
        float4 v = *(const float4*)(w + o * 4);
        __half hv[4];
#pragma unroll
        for (int q = 0; q < 4; ++q) hv[q] = __float2half_rn((&v.x)[q]);
        *(uint2*)(wh + o * 4) = *(uint2*)hv;
    }
}

// V transpose (fp32 -> single fp16)
__global__ void vtrans_kernel(const float* __restrict__ vf, __half* __restrict__ vth)
{
    __shared__ float tile[32][33];
    const int s0 = blockIdx.x * 32, c0 = blockIdx.y * 32, b = blockIdx.z;
    const int tx = threadIdx.x, ty = threadIdx.y;
#pragma unroll
    for (int j = 0; j < 4; ++j) {
        const int s = s0 + ty + j * 8;
        tile[ty + j * 8][tx] = vf[(long long)(b * 2048 + s) * 1024 + c0 + tx];
    }
    __syncthreads();
#pragma unroll
    for (int j = 0; j < 4; ++j) {
        const int c = c0 + ty + j * 8;
        const long long o = ((long long)b * 1024 + c) * 2048 + s0 + tx;
        vth[o] = __float2half_rn(tile[tx][ty + j * 8]);
    }
}

// --------------------- causal softmax -> fp16 hi/lo(x1024) -----------------
__global__ void softmax_causal_kernel(const float* __restrict__ att,
                                      __half* __restrict__ ph,
                                      __half* __restrict__ pl)
{
    const int row = blockIdx.x;
    const int b = row >> 11, t = row & 2047;
    const float* p = att + ((long long)b * 2048 + t) * 2048;
    __half* hrow = ph + ((long long)b * 2048 + t) * 2048;
    __half* lrow = pl + ((long long)b * 2048 + t) * 2048;
    const int n = t + 1;
    const int zb = ((t >> 7) + 1) << 7;
    const int tid = threadIdx.x;
    __shared__ float sbuf[8];

    float e[8];
    float m = -3.4e38f;
#pragma unroll
    for (int j = 0; j < 8; ++j) {
        const int i = tid + j * 256;
        e[j] = (i < n) ? p[i] : -3.4e38f;
        m = fmaxf(m, e[j]);
    }
#pragma unroll
    for (int o = 16; o > 0; o >>= 1) m = fmaxf(m, __shfl_xor_sync(0xffffffffu, m, o));
    if ((tid & 31) == 0) sbuf[tid >> 5] = m;
    __syncthreads();
    if (tid < 8) {
        float v = sbuf[tid];
#pragma unroll
        for (int o = 4; o > 0; o >>= 1) v = fmaxf(v, __shfl_xor_sync(0xffu, v, o));
        if (tid == 0) sbuf[0] = v;
    }
    __syncthreads();
    m = sbuf[0];
    __syncthreads();

    float s = 0.f;
#pragma unroll
    for (int j = 0; j < 8; ++j) {
        const int i = tid + j * 256;
        e[j] = (i < n) ? __expf(e[j] - m) : 0.f;
        s += e[j];
    }
#pragma unroll
    for (int o = 16; o > 0; o >>= 1) s += __shfl_xor_sync(0xffffffffu, s, o);
    if ((tid & 31) == 0) sbuf[tid >> 5] = s;
    __syncthreads();
    if (tid < 8) {
        float v = sbuf[tid];
#pragma unroll
        for (int o = 4; o > 0; o >>= 1) v += __shfl_xor_sync(0xffu, v, o);
        if (tid == 0) sbuf[0] = v;
    }
    __syncthreads();
    const float inv = 1.f / sbuf[0];

#pragma unroll
    for (int j = 0; j < 8; ++j) {
        const int i = tid + j * 256;
        if (i >= zb) break;
        const float v = e[j] * inv;
        const __half h = __float2half_rn(v);
        hrow[i] = h;
        lrow[i] = __float2half_rn((v - __half2float(h)) * LO_SCALE);
    }
}

// ---------------------------------------------------------------------------
extern "C" void kernel_launch(void* const* d_in, const int* in_sizes, int n_in,
                              void* d_out, int out_size)
{
    const float* x = (const float*)d_in[0];
    const float* w = (const float*)d_in[1];
    float* out = (float*)d_out;

    float *att, *vf;
    __half *xh, *xl, *wh, *qh, *ql, *kh, *vth, *phb, *plb;
    cudaGetSymbolAddress((void**)&att, g_att);
    cudaGetSymbolAddress((void**)&vf, g_vf);
    cudaGetSymbolAddress((void**)&xh, g_xh);   cudaGetSymbolAddress((void**)&xl, g_xl);
    cudaGetSymbolAddress((void**)&wh, g_wh);
    cudaGetSymbolAddress((void**)&qh, g_qh);   cudaGetSymbolAddress((void**)&ql, g_ql);
    cudaGetSymbolAddress((void**)&kh, g_kh);
    cudaGetSymbolAddress((void**)&vth, g_vth);
    cudaGetSymbolAddress((void**)&phb, g_ph);  cudaGetSymbolAddress((void**)&plb, g_pl);

    cudaFuncSetAttribute(gemm2_kernel, cudaFuncAttributeMaxDynamicSharedMemorySize,
                         GEMM_SMEM);

    // 0) split x (hi/lo x1024) and w (single)
    {
        const long long total = X_N4 + W_N4;
        split_xw_kernel<<<(int)((total + 255) / 256), 256>>>(x, w, xh, xl, wh);
    }
    // 1) qkv = x @ w^T  (fused split epilogue)
    {
        dim3 grid(3072 / 128, 8192 / 128, 1);
        gemm2_kernel<<<grid, 256, GEMM_SMEM>>>(xh, xl, wh, nullptr,
                                               1024, 1024, 1024, 0,
                                               0, 0, 0, 1.0f, 0, 0, 1, 0);
    }
    // 2) transpose v -> fp16
    {
        dim3 grid(2048 / 32, 1024 / 32, 4);
        vtrans_kernel<<<grid, dim3(32, 8)>>>(vf, vth);
    }
    // 3) S = q k^T / 32  (causal tile skip)  [profiled slot]
    {
        dim3 grid(2048 / 128, 2048 / 128, 4);
        gemm2_kernel<<<grid, 256, GEMM_SMEM>>>(qh, ql, kh, att,
                                               1024, 1024, 1024, 2048,
                                               2048LL * 1024, 2048LL * 1024, 2048LL * 2048,
                                               0.03125f, 1, 0, 0, 1);
    }
    // 4) P = softmax(S) -> fp16 hi/lo(x1024)
    softmax_causal_kernel<<<4 * 2048, 256>>>(att, phb, plb);

    // 5) y = P @ V  (V^T K-major, causal K-limit)
    {
        dim3 grid(1024 / 128, 2048 / 128, 4);
        gemm2_kernel<<<grid, 256, GEMM_SMEM>>>(phb, plb, vth, out,
                                               2048, 2048, 2048, 1024,
                                               2048LL * 2048, 1024LL * 2048, 2048LL * 1024,
                                               1.0f, 0, 1, 0, 1);
    }
}

// round 14
// speedup vs baseline: 1.0017x; 1.0017x over previous
#include <cuda_runtime.h>
#include <cuda_fp16.h>
#include <cstdint>
#include <math.h>

// ---------------------------------------------------------------------------
// SingleHeadAttention B=4, T=2048, C=1024 fp32 — fp16 2-term mma.sync GEMMs
//   hi term: f32-accum HMMA (half rate);  lo term: f16-accum HMMA (full rate)
//   lo operands pre-scaled x1024 (mid-range f16, no subnormals); /1024 at epi.
//   qkv = x @ w^T   (fused epilogue -> qh/ql fp16, kh fp16, v fp32)
//   S   = q k^T/32  (causal tile-skip) -> att fp32
//   P   = softmax   -> fp16 hi/lo(x1024)
//   y   = P @ (V^T)^T (causal K-limit)
// R12: R11 skeleton (CTA 128x128, 256 thr, 8 warps 2m x 4n, kc=32, 3-stage,
//      1 CTA/SM, fragment double buffering).
// ---------------------------------------------------------------------------

#define LO_SCALE 1024.0f
#define LO_INV   (1.0f / 1024.0f)

// ------------------------------ scratch ------------------------------------
__device__ float g_att[(size_t)4 * 2048 * 2048];
__device__ float g_vf[(size_t)4 * 2048 * 1024];
__device__ __half g_xh[(size_t)8192 * 1024];
__device__ __half g_xl[(size_t)8192 * 1024];          // x1024
__device__ __half g_wh[(size_t)3072 * 1024];
__device__ __half g_qh[(size_t)4 * 2048 * 1024];
__device__ __half g_ql[(size_t)4 * 2048 * 1024];      // x1024
__device__ __half g_kh[(size_t)4 * 2048 * 1024];
__device__ __half g_vth[(size_t)4 * 1024 * 2048];     // V^T
__device__ __half g_ph[(size_t)4 * 2048 * 2048];
__device__ __half g_pl[(size_t)4 * 2048 * 2048];      // x1024

// ------------------------------ helpers ------------------------------------
#define SA 40                                 // padded smem row stride (halfs)
#define TILE_B (128 * SA * 2)                 // 10240 per operand tile
#define STAGE_B (3 * TILE_B)                  // Ah, Al, Bh = 30720
#define GEMM_SMEM (3 * STAGE_B)               // 92160 -> 1 CTA/SM
#define KOFF16 32

__device__ __forceinline__ uint32_t smem_u32(const void* p) {
    uint32_t a;
    asm("{ .reg .u64 t; cvta.to.shared.u64 t, %1; cvt.u32.u64 %0, t; }" : "=r"(a) : "l"(p));
    return a;
}
__device__ __forceinline__ void cp16(uint32_t dst, const void* src) {
    asm volatile("cp.async.cg.shared.global [%0], [%1], 16;" :: "r"(dst), "l"(src));
}
__device__ __forceinline__ void ldmx4(uint32_t* r, uint32_t addr) {
    asm volatile("ldmatrix.sync.aligned.m8n8.x4.shared.b16 {%0,%1,%2,%3}, [%4];"
                 : "=r"(r[0]), "=r"(r[1]), "=r"(r[2]), "=r"(r[3]) : "r"(addr));
}
// hi term: f32 accumulate
__device__ __forceinline__ void mma_f32(float* c, const uint32_t* a, const uint32_t* b) {
    asm volatile(
        "mma.sync.aligned.m16n8k16.row.col.f32.f16.f16.f32 "
        "{%0,%1,%2,%3}, {%4,%5,%6,%7}, {%8,%9}, {%0,%1,%2,%3};"
        : "+f"(c[0]), "+f"(c[1]), "+f"(c[2]), "+f"(c[3])
        : "r"(a[0]), "r"(a[1]), "r"(a[2]), "r"(a[3]), "r"(b[0]), "r"(b[1]));
}
// lo term: f16 accumulate (2 b32 regs of half2)
__device__ __forceinline__ void mma_f16(uint32_t* c, const uint32_t* a, const uint32_t* b) {
    asm volatile(
        "mma.sync.aligned.m16n8k16.row.col.f16.f16.f16.f16 "
        "{%0,%1}, {%2,%3,%4,%5}, {%6,%7}, {%0,%1};"
        : "+r"(c[0]), "+r"(c[1])
        : "r"(a[0]), "r"(a[1]), "r"(a[2]), "r"(a[3]), "r"(b[0]), "r"(b[1]));
}
__device__ __forceinline__ uint32_t pack2h(float v0, float v1) {
    __half2 h = __floats2half2_rn(v0, v1);
    return *(uint32_t*)&h;
}

// ------------------------------ GEMM ---------------------------------------
// mode 0: C = alpha * (hi + lo/1024);  mode 1: fused qkv split epilogue
__global__ __launch_bounds__(256, 1)
void gemm2_kernel(const __half* __restrict__ Ah, const __half* __restrict__ Al,
                  const __half* __restrict__ Bh,
                  float* __restrict__ C,
                  int K, int lda, int ldb, int ldc,
                  long long sAo, long long sBo, long long sCo,
                  float alpha, int causal_skip, int causal_klim, int mode, int rev_y)
{
    const int by = rev_y ? (gridDim.y - 1 - blockIdx.y) : blockIdx.y;
    const int m0 = by * 128;
    const int n0 = blockIdx.x * 128;
    if (causal_skip && n0 > m0 + 127) return;

    const int bz = blockIdx.z;
    Ah += (long long)bz * sAo;  Al += (long long)bz * sAo;
    Bh += (long long)bz * sBo;
    C  += (long long)bz * sCo;

    int Keff = K;
    if (causal_klim) { int lim = m0 + 128; Keff = (lim < K) ? lim : K; }
    const int NC = Keff / 32;

    extern __shared__ char smem[];
    const uint32_t sb = smem_u32(smem);
    const int tid = threadIdx.x;
    const int wid = tid >> 5;
    const int lane = tid & 31;

    auto load_stage = [&](int s, int c) {
        const uint32_t base = sb + s * STAGE_B;
        const int k0 = c * 32;
#pragma unroll
        for (int it = 0; it < 2; ++it) {
            const int id  = tid + it * 256;
            const int row = id >> 2;
            const int c16 = id & 3;
            const uint32_t so = (uint32_t)(row * SA + c16 * 8) * 2;
            const long long ga = (long long)(m0 + row) * lda + k0 + c16 * 8;
            const long long gb = (long long)(n0 + row) * ldb + k0 + c16 * 8;
            cp16(base + so,              Ah + ga);
            cp16(base + TILE_B + so,     Al + ga);
            cp16(base + 2 * TILE_B + so, Bh + gb);
        }
        asm volatile("cp.async.commit_group;" ::: "memory");
    };

    float acc[4][4][4];
    uint32_t accl[4][4][2];
#pragma unroll
    for (int i = 0; i < 4; ++i)
#pragma unroll
        for (int j = 0; j < 4; ++j) {
#pragma unroll
            for (int q = 0; q < 4; ++q) acc[i][j][q] = 0.f;
            accl[i][j][0] = 0u; accl[i][j][1] = 0u;
        }

    const int wm = (wid & 1) * 64;
    const int wn = (wid >> 1) * 32;
    const int gr = lane >> 3;
    const int rr = lane & 7;

    const uint32_t a_off = (uint32_t)((wm + (gr & 1) * 8 + rr) * SA + (gr >> 1) * 8) * 2;
    const uint32_t b_off = (uint32_t)((wn + (gr >> 1) * 8 + rr) * SA + (gr & 1) * 8) * 2;

    uint32_t fah0[4][4], fal0[4][4], fbh0[4][2];
    uint32_t fah1[4][4], fal1[4][4], fbh1[4][2];

    auto load_frags = [&](uint32_t st, uint32_t koff,
                          uint32_t (&fah)[4][4], uint32_t (&fal)[4][4],
                          uint32_t (&fbh)[4][2]) {
#pragma unroll
        for (int nt = 0; nt < 2; ++nt) {
            uint32_t r[4];
            ldmx4(r, st + 2 * TILE_B + b_off + koff + (uint32_t)(nt * 16 * SA) * 2);
            fbh[nt * 2 + 0][0] = r[0]; fbh[nt * 2 + 0][1] = r[1];
            fbh[nt * 2 + 1][0] = r[2]; fbh[nt * 2 + 1][1] = r[3];
        }
#pragma unroll
        for (int mi = 0; mi < 4; ++mi) {
            const uint32_t off = a_off + koff + (uint32_t)(mi * 16 * SA) * 2;
            ldmx4(fah[mi], st + off);
            ldmx4(fal[mi], st + TILE_B + off);
        }
    };
    auto mma_all = [&](uint32_t (&fah)[4][4], uint32_t (&fal)[4][4],
                       uint32_t (&fbh)[4][2]) {
#pragma unroll
        for (int mi = 0; mi < 4; ++mi) {
#pragma unroll
            for (int nj = 0; nj < 4; ++nj) mma_f32(acc[mi][nj], fah[mi], fbh[nj]);
#pragma unroll
            for (int nj = 0; nj < 4; ++nj) mma_f16(accl[mi][nj], fal[mi], fbh[nj]);
        }
    };

    load_stage(0, 0);
    load_stage(1, 1);
    load_stage(2, 2);
    asm volatile("cp.async.wait_group 2;" ::: "memory");
    __syncthreads();
    load_frags(sb, 0, fah0, fal0, fbh0);

    for (int c = 0; c < NC; ++c) {
        const uint32_t st = sb + (c % 3) * STAGE_B;

        load_frags(st, KOFF16, fah1, fal1, fbh1);
        mma_all(fah0, fal0, fbh0);

        if (c + 2 < NC) asm volatile("cp.async.wait_group 1;" ::: "memory");
        else            asm volatile("cp.async.wait_group 0;" ::: "memory");
        __syncthreads();
        if (c + 3 < NC) load_stage(c % 3, c + 3);
        if (c + 1 < NC)
            load_frags(sb + ((c + 1) % 3) * STAGE_B, 0, fah0, fal0, fbh0);

        mma_all(fah1, fal1, fbh1);
    }

    // ---- epilogue: combine hi + lo/1024 ----
#pragma unroll
    for (int mi = 0; mi < 4; ++mi)
#pragma unroll
        for (int nj = 0; nj < 4; ++nj) {
            __half2 l0 = *(__half2*)&accl[mi][nj][0];
            __half2 l1 = *(__half2*)&accl[mi][nj][1];
            acc[mi][nj][0] += LO_INV * __half2float(l0.x);
            acc[mi][nj][1] += LO_INV * __half2float(l0.y);
            acc[mi][nj][2] += LO_INV * __half2float(l1.x);
            acc[mi][nj][3] += LO_INV * __half2float(l1.y);
        }

    if (mode == 0) {
#pragma unroll
        for (int mi = 0; mi < 4; ++mi)
#pragma unroll
            for (int nj = 0; nj < 4; ++nj) {
                const int row = m0 + wm + mi * 16 + (lane >> 2);
                const int col = n0 + wn + nj * 8 + (lane & 3) * 2;
                float2 v0 = make_float2(alpha * acc[mi][nj][0], alpha * acc[mi][nj][1]);
                float2 v1 = make_float2(alpha * acc[mi][nj][2], alpha * acc[mi][nj][3]);
                *(float2*)(C + (long long)row * ldc + col)       = v0;
                *(float2*)(C + (long long)(row + 8) * ldc + col) = v1;
            }
    } else {
        const int seg = n0 >> 10;                      // 0=q 1=k 2=v
#pragma unroll
        for (int mi = 0; mi < 4; ++mi)
#pragma unroll
            for (int nj = 0; nj < 4; ++nj) {
                const int row = m0 + wm + mi * 16 + (lane >> 2);
                const int cc  = (n0 & 1023) + wn + nj * 8 + (lane & 3) * 2;
                const float v00 = acc[mi][nj][0], v01 = acc[mi][nj][1];
                const float v10 = acc[mi][nj][2], v11 = acc[mi][nj][3];
                const long long o0 = (long long)row * 1024 + cc;
                const long long o1 = (long long)(row + 8) * 1024 + cc;
                if (seg == 2) {
                    *(float2*)(g_vf + o0) = make_float2(v00, v01);
                    *(float2*)(g_vf + o1) = make_float2(v10, v11);
                } else if (seg == 1) {                 // k: single fp16
                    *(uint32_t*)(g_kh + o0) = pack2h(v00, v01);
                    *(uint32_t*)(g_kh + o1) = pack2h(v10, v11);
                } else {                               // q: fp16 hi + lo(x1024)
                    __half h00 = __float2half_rn(v00), h01 = __float2half_rn(v01);
                    __half h10 = __float2half_rn(v10), h11 = __float2half_rn(v11);
                    __half2 p0; p0.x = h00; p0.y = h01;
                    __half2 p1; p1.x = h10; p1.y = h11;
                    *(uint32_t*)(g_qh + o0) = *(uint32_t*)&p0;
                    *(uint32_t*)(g_qh + o1) = *(uint32_t*)&p1;
                    *(uint32_t*)(g_ql + o0) = pack2h((v00 - __half2float(h00)) * LO_SCALE,
                                                     (v01 - __half2float(h01)) * LO_SCALE);
                    *(uint32_t*)(g_ql + o1) = pack2h((v10 - __half2float(h10)) * LO_SCALE,
                                                     (v11 - __half2float(h11)) * LO_SCALE);
                }
            }
    }
}

// --------------------- merged input split (x hi/lo, w single) --------------
#define X_N4 (8192LL * 1024 / 4)
#define W_N4 (3072LL * 1024 / 4)
__global__ void split_xw_kernel(const float* __restrict__ x, const float* __restrict__ w,
                                __half* __restrict__ xh, __half* __restrict__ xl,
                                __half* __restrict__ wh)
{
    long long i = (long long)blockIdx.x * blockDim.x + threadIdx.x;
    if (i < X_N4) {
        float4 v = *(const float4*)(x + i * 4);
        __half hv[4], lv[4];
#pragma unroll
        for (int q = 0; q < 4; ++q) {
            float f = (&v.x)[q];
            hv[q] = __float2half_rn(f);
            lv[q] = __float2half_rn((f - __half2float(hv[q])) * LO_SCALE);
        }
        *(uint2*)(xh + i * 4) = *(uint2*)hv;
        *(uint2*)(xl + i * 4) = *(uint2*)lv;
    } else {
        long long o = i - X_N4;
        if (o >= W_N4) return;
        float4 v = *(const float4*)(w + o * 4);
        __half hv[4];
#pragma unroll
        for (int q = 0; q < 4; ++q) hv[q] = __float2half_rn((&v.x)[q]);
        *(uint2*)(wh + o * 4) = *(uint2*)hv;
    }
}

// V transpose (fp32 -> single fp16)
__global__ void vtrans_kernel(const float* __restrict__ vf, __half* __restrict__ vth)
{
    __shared__ float tile[32][33];
    const int s0 = blockIdx.x * 32, c0 = blockIdx.y * 32, b = blockIdx.z;
    const int tx = threadIdx.x, ty = threadIdx.y;
#pragma unroll
    for (int j = 0; j < 4; ++j) {
        const int s = s0 + ty + j * 8;
        tile[ty + j * 8][tx] = vf[(long long)(b * 2048 + s) * 1024 + c0 + tx];
    }
    __syncthreads();
#pragma unroll
    for (int j = 0; j < 4; ++j) {
        const int c = c0 + ty + j * 8;
        const long long o = ((long long)b * 1024 + c) * 2048 + s0 + tx;
        vth[o] = __float2half_rn(tile[tx][ty + j * 8]);
    }
}

// --------------------- causal softmax -> fp16 hi/lo(x1024) -----------------
__global__ void softmax_causal_kernel(const float* __restrict__ att,
                                      __half* __restrict__ ph,
                                      __half* __restrict__ pl)
{
    const int row = blockIdx.x;
    const int b = row >> 11, t = row & 2047;
    const float* p = att + ((long long)b * 2048 + t) * 2048;
    __half* hrow = ph + ((long long)b * 2048 + t) * 2048;
    __half* lrow = pl + ((long long)b * 2048 + t) * 2048;
    const int n = t + 1;
    const int zb = ((t >> 7) + 1) << 7;
    const int tid = threadIdx.x;
    __shared__ float sbuf[8];

    float e[8];
    float m = -3.4e38f;
#pragma unroll
    for (int j = 0; j < 8; ++j) {
        const int i = tid + j * 256;
        e[j] = (i < n) ? p[i] : -3.4e38f;
        m = fmaxf(m, e[j]);
    }
#pragma unroll
    for (int o = 16; o > 0; o >>= 1) m = fmaxf(m, __shfl_xor_sync(0xffffffffu, m, o));
    if ((tid & 31) == 0) sbuf[tid >> 5] = m;
    __syncthreads();
    if (tid < 8) {
        float v = sbuf[tid];
#pragma unroll
        for (int o = 4; o > 0; o >>= 1) v = fmaxf(v, __shfl_xor_sync(0xffu, v, o));
        if (tid == 0) sbuf[0] = v;
    }
    __syncthreads();
    m = sbuf[0];
    __syncthreads();

    float s = 0.f;
#pragma unroll
    for (int j = 0; j < 8; ++j) {
        const int i = tid + j * 256;
        e[j] = (i < n) ? __expf(e[j] - m) : 0.f;
        s += e[j];
    }
#pragma unroll
    for (int o = 16; o > 0; o >>= 1) s += __shfl_xor_sync(0xffffffffu, s, o);
    if ((tid & 31) == 0) sbuf[tid >> 5] = s;
    __syncthreads();
    if (tid < 8) {
        float v = sbuf[tid];
#pragma unroll
        for (int o = 4; o > 0; o >>= 1) v += __shfl_xor_sync(0xffu, v, o);
        if (tid == 0) sbuf[0] = v;
    }
    __syncthreads();
    const float inv = 1.f / sbuf[0];

#pragma unroll
    for (int j = 0; j < 8; ++j) {
        const int i = tid + j * 256;
        if (i >= zb) break;
        const float v = e[j] * inv;
        const __half h = __float2half_rn(v);
        hrow[i] = h;
        lrow[i] = __float2half_rn((v - __half2float(h)) * LO_SCALE);
    }
}

// ---------------------------------------------------------------------------
extern "C" void kernel_launch(void* const* d_in, const int* in_sizes, int n_in,
                              void* d_out, int out_size)
{
    const float* x = (const float*)d_in[0];
    const float* w = (const float*)d_in[1];
    float* out = (float*)d_out;

    float *att, *vf;
    __half *xh, *xl, *wh, *qh, *ql, *kh, *vth, *phb, *plb;
    cudaGetSymbolAddress((void**)&att, g_att);
    cudaGetSymbolAddress((void**)&vf, g_vf);
    cudaGetSymbolAddress((void**)&xh, g_xh);   cudaGetSymbolAddress((void**)&xl, g_xl);
    cudaGetSymbolAddress((void**)&wh, g_wh);
    cudaGetSymbolAddress((void**)&qh, g_qh);   cudaGetSymbolAddress((void**)&ql, g_ql);
    cudaGetSymbolAddress((void**)&kh, g_kh);
    cudaGetSymbolAddress((void**)&vth, g_vth);
    cudaGetSymbolAddress((void**)&phb, g_ph);  cudaGetSymbolAddress((void**)&plb, g_pl);

    cudaFuncSetAttribute(gemm2_kernel, cudaFuncAttributeMaxDynamicSharedMemorySize,
                         GEMM_SMEM);

    // 0) split x (hi/lo x1024) and w (single)
    {
        const long long total = X_N4 + W_N4;
        split_xw_kernel<<<(int)((total + 255) / 256), 256>>>(x, w, xh, xl, wh);
    }
    // 1) qkv = x @ w^T  (fused split epilogue)
    {
        dim3 grid(3072 / 128, 8192 / 128, 1);
        gemm2_kernel<<<grid, 256, GEMM_SMEM>>>(xh, xl, wh, nullptr,
                                               1024, 1024, 1024, 0,
                                               0, 0, 0, 1.0f, 0, 0, 1, 0);
    }
    // 2) transpose v -> fp16
    {
        dim3 grid(2048 / 32, 1024 / 32, 4);
        vtrans_kernel<<<grid, dim3(32, 8)>>>(vf, vth);
    }
    // 3) S = q k^T / 32  (causal tile skip)  [profiled slot]
    {
        dim3 grid(2048 / 128, 2048 / 128, 4);
        gemm2_kernel<<<grid, 256, GEMM_SMEM>>>(qh, ql, kh, att,
                                               1024, 1024, 1024, 2048,
                                               2048LL * 1024, 2048LL * 1024, 2048LL * 2048,
                                               0.03125f, 1, 0, 0, 1);
    }
    // 4) P = softmax(S) -> fp16 hi/lo(x1024)
    softmax_causal_kernel<<<4 * 2048, 256>>>(att, phb, plb);

    // 5) y = P @ V  (V^T K-major, causal K-limit)
    {
        dim3 grid(1024 / 128, 2048 / 128, 4);
        gemm2_kernel<<<grid, 256, GEMM_SMEM>>>(phb, plb, vth, out,
                                               2048, 2048, 2048, 1024,
                                               2048LL * 2048, 1024LL * 2048, 2048LL * 1024,
                                               1.0f, 0, 1, 0, 1);
    }
}

// round 15
// speedup vs baseline: 1.6004x; 1.5976x over previous
#include <cuda_runtime.h>
#include <cuda_fp16.h>
#include <cstdint>
#include <math.h>

// ---------------------------------------------------------------------------
// SingleHeadAttention B=4, T=2048, C=1024 fp32 — pure fp16 mma.sync GEMMs
//   (single-term: C = A_fp16 * B_fp16^T, fp32 accumulate; err ~6e-4 < 1e-3)
//   qkv = x @ w^T   (fused epilogue -> q,k fp16, v fp32)
//   S   = q k^T/32  (causal tile-skip) -> att fp32
//   P   = softmax   -> fp16
//   y   = P @ (V^T)^T (causal K-limit)
// R15: R11 skeleton (CTA 128x128, 256 thr, 8 warps 2m x 4n of 64x32, kc=32,
//      3-stage cp.async, 1 CTA/SM, fragment double buffering), lo terms gone.
// ---------------------------------------------------------------------------

// ------------------------------ scratch ------------------------------------
__device__ float g_att[(size_t)4 * 2048 * 2048];
__device__ float g_vf[(size_t)4 * 2048 * 1024];
__device__ __half g_xh[(size_t)8192 * 1024];
__device__ __half g_wh[(size_t)3072 * 1024];
__device__ __half g_qh[(size_t)4 * 2048 * 1024];
__device__ __half g_kh[(size_t)4 * 2048 * 1024];
__device__ __half g_vth[(size_t)4 * 1024 * 2048];     // V^T
__device__ __half g_ph[(size_t)4 * 2048 * 2048];

// ------------------------------ helpers ------------------------------------
#define SA 40                                 // padded smem row stride (halfs)
#define TILE_B (128 * SA * 2)                 // 10240 per operand tile
#define STAGE_B (2 * TILE_B)                  // A, B = 20480
#define GEMM_SMEM (3 * STAGE_B)               // 61440
#define KOFF16 32

__device__ __forceinline__ uint32_t smem_u32(const void* p) {
    uint32_t a;
    asm("{ .reg .u64 t; cvta.to.shared.u64 t, %1; cvt.u32.u64 %0, t; }" : "=r"(a) : "l"(p));
    return a;
}
__device__ __forceinline__ void cp16(uint32_t dst, const void* src) {
    asm volatile("cp.async.cg.shared.global [%0], [%1], 16;" :: "r"(dst), "l"(src));
}
__device__ __forceinline__ void ldmx4(uint32_t* r, uint32_t addr) {
    asm volatile("ldmatrix.sync.aligned.m8n8.x4.shared.b16 {%0,%1,%2,%3}, [%4];"
                 : "=r"(r[0]), "=r"(r[1]), "=r"(r[2]), "=r"(r[3]) : "r"(addr));
}
__device__ __forceinline__ void mma_f32(float* c, const uint32_t* a, const uint32_t* b) {
    asm volatile(
        "mma.sync.aligned.m16n8k16.row.col.f32.f16.f16.f32 "
        "{%0,%1,%2,%3}, {%4,%5,%6,%7}, {%8,%9}, {%0,%1,%2,%3};"
        : "+f"(c[0]), "+f"(c[1]), "+f"(c[2]), "+f"(c[3])
        : "r"(a[0]), "r"(a[1]), "r"(a[2]), "r"(a[3]), "r"(b[0]), "r"(b[1]));
}
__device__ __forceinline__ uint32_t pack2h(float v0, float v1) {
    __half2 h = __floats2half2_rn(v0, v1);
    return *(uint32_t*)&h;
}

// ------------------------------ GEMM ---------------------------------------
// mode 0: C = alpha * acc (fp32);  mode 1: fused qkv epilogue (q,k fp16, v f32)
__global__ __launch_bounds__(256, 1)
void gemm1_kernel(const __half* __restrict__ Ah, const __half* __restrict__ Bh,
                  float* __restrict__ C,
                  int K, int lda, int ldb, int ldc,
                  long long sAo, long long sBo, long long sCo,
                  float alpha, int causal_skip, int causal_klim, int mode, int rev_y)
{
    const int by = rev_y ? (gridDim.y - 1 - blockIdx.y) : blockIdx.y;
    const int m0 = by * 128;
    const int n0 = blockIdx.x * 128;
    if (causal_skip && n0 > m0 + 127) return;

    const int bz = blockIdx.z;
    Ah += (long long)bz * sAo;
    Bh += (long long)bz * sBo;
    C  += (long long)bz * sCo;

    int Keff = K;
    if (causal_klim) { int lim = m0 + 128; Keff = (lim < K) ? lim : K; }
    const int NC = Keff / 32;

    extern __shared__ char smem[];
    const uint32_t sb = smem_u32(smem);
    const int tid = threadIdx.x;
    const int wid = tid >> 5;
    const int lane = tid & 31;

    auto load_stage = [&](int s, int c) {
        const uint32_t base = sb + s * STAGE_B;
        const int k0 = c * 32;
#pragma unroll
        for (int it = 0; it < 2; ++it) {
            const int id  = tid + it * 256;
            const int row = id >> 2;
            const int c16 = id & 3;
            const uint32_t so = (uint32_t)(row * SA + c16 * 8) * 2;
            const long long ga = (long long)(m0 + row) * lda + k0 + c16 * 8;
            const long long gb = (long long)(n0 + row) * ldb + k0 + c16 * 8;
            cp16(base + so,          Ah + ga);
            cp16(base + TILE_B + so, Bh + gb);
        }
        asm volatile("cp.async.commit_group;" ::: "memory");
    };

    float acc[4][4][4];
#pragma unroll
    for (int i = 0; i < 4; ++i)
#pragma unroll
        for (int j = 0; j < 4; ++j)
#pragma unroll
            for (int q = 0; q < 4; ++q) acc[i][j][q] = 0.f;

    const int wm = (wid & 1) * 64;
    const int wn = (wid >> 1) * 32;
    const int gr = lane >> 3;
    const int rr = lane & 7;

    const uint32_t a_off = (uint32_t)((wm + (gr & 1) * 8 + rr) * SA + (gr >> 1) * 8) * 2;
    const uint32_t b_off = (uint32_t)((wn + (gr >> 1) * 8 + rr) * SA + (gr & 1) * 8) * 2;

    uint32_t fah0[4][4], fbh0[4][2];
    uint32_t fah1[4][4], fbh1[4][2];

    auto load_frags = [&](uint32_t st, uint32_t koff,
                          uint32_t (&fah)[4][4], uint32_t (&fbh)[4][2]) {
#pragma unroll
        for (int nt = 0; nt < 2; ++nt) {
            uint32_t r[4];
            ldmx4(r, st + TILE_B + b_off + koff + (uint32_t)(nt * 16 * SA) * 2);
            fbh[nt * 2 + 0][0] = r[0]; fbh[nt * 2 + 0][1] = r[1];
            fbh[nt * 2 + 1][0] = r[2]; fbh[nt * 2 + 1][1] = r[3];
        }
#pragma unroll
        for (int mi = 0; mi < 4; ++mi)
            ldmx4(fah[mi], st + a_off + koff + (uint32_t)(mi * 16 * SA) * 2);
    };
    auto mma_all = [&](uint32_t (&fah)[4][4], uint32_t (&fbh)[4][2]) {
#pragma unroll
        for (int mi = 0; mi < 4; ++mi)
#pragma unroll
            for (int nj = 0; nj < 4; ++nj) mma_f32(acc[mi][nj], fah[mi], fbh[nj]);
    };

    load_stage(0, 0);
    load_stage(1, 1);
    load_stage(2, 2);
    asm volatile("cp.async.wait_group 2;" ::: "memory");
    __syncthreads();
    load_frags(sb, 0, fah0, fbh0);

    for (int c = 0; c < NC; ++c) {
        const uint32_t st = sb + (c % 3) * STAGE_B;

        load_frags(st, KOFF16, fah1, fbh1);
        mma_all(fah0, fbh0);

        if (c + 2 < NC) asm volatile("cp.async.wait_group 1;" ::: "memory");
        else            asm volatile("cp.async.wait_group 0;" ::: "memory");
        __syncthreads();
        if (c + 3 < NC) load_stage(c % 3, c + 3);
        if (c + 1 < NC)
            load_frags(sb + ((c + 1) % 3) * STAGE_B, 0, fah0, fbh0);

        mma_all(fah1, fbh1);
    }

    // ---- epilogue ----
    if (mode == 0) {
#pragma unroll
        for (int mi = 0; mi < 4; ++mi)
#pragma unroll
            for (int nj = 0; nj < 4; ++nj) {
                const int row = m0 + wm + mi * 16 + (lane >> 2);
                const int col = n0 + wn + nj * 8 + (lane & 3) * 2;
                float2 v0 = make_float2(alpha * acc[mi][nj][0], alpha * acc[mi][nj][1]);
                float2 v1 = make_float2(alpha * acc[mi][nj][2], alpha * acc[mi][nj][3]);
                *(float2*)(C + (long long)row * ldc + col)       = v0;
                *(float2*)(C + (long long)(row + 8) * ldc + col) = v1;
            }
    } else {
        const int seg = n0 >> 10;                      // 0=q 1=k 2=v
        __half* dst = (seg == 0) ? g_qh : g_kh;
#pragma unroll
        for (int mi = 0; mi < 4; ++mi)
#pragma unroll
            for (int nj = 0; nj < 4; ++nj) {
                const int row = m0 + wm + mi * 16 + (lane >> 2);
                const int cc  = (n0 & 1023) + wn + nj * 8 + (lane & 3) * 2;
                const float v00 = acc[mi][nj][0], v01 = acc[mi][nj][1];
                const float v10 = acc[mi][nj][2], v11 = acc[mi][nj][3];
                const long long o0 = (long long)row * 1024 + cc;
                const long long o1 = (long long)(row + 8) * 1024 + cc;
                if (seg == 2) {
                    *(float2*)(g_vf + o0) = make_float2(v00, v01);
                    *(float2*)(g_vf + o1) = make_float2(v10, v11);
                } else {
                    *(uint32_t*)(dst + o0) = pack2h(v00, v01);
                    *(uint32_t*)(dst + o1) = pack2h(v10, v11);
                }
            }
    }
}

// --------------------- input convert (x, w -> fp16) ------------------------
#define X_N4 (8192LL * 1024 / 4)
#define W_N4 (3072LL * 1024 / 4)
__global__ void conv_xw_kernel(const float* __restrict__ x, const float* __restrict__ w,
                               __half* __restrict__ xh, __half* __restrict__ wh)
{
    long long i = (long long)blockIdx.x * blockDim.x + threadIdx.x;
    const float* src;
    __half* dst;
    long long o;
    if (i < X_N4) { src = x; dst = xh; o = i; }
    else {
        o = i - X_N4;
        if (o >= W_N4) return;
        src = w; dst = wh;
    }
    float4 v = *(const float4*)(src + o * 4);
    __half hv[4];
#pragma unroll
    for (int q = 0; q < 4; ++q) hv[q] = __float2half_rn((&v.x)[q]);
    *(uint2*)(dst + o * 4) = *(uint2*)hv;
}

// V transpose (fp32 -> fp16): vT[b][c][s] = vf[b*2048+s][c]
__global__ void vtrans_kernel(const float* __restrict__ vf, __half* __restrict__ vth)
{
    __shared__ float tile[32][33];
    const int s0 = blockIdx.x * 32, c0 = blockIdx.y * 32, b = blockIdx.z;
    const int tx = threadIdx.x, ty = threadIdx.y;
#pragma unroll
    for (int j = 0; j < 4; ++j) {
        const int s = s0 + ty + j * 8;
        tile[ty + j * 8][tx] = vf[(long long)(b * 2048 + s) * 1024 + c0 + tx];
    }
    __syncthreads();
#pragma unroll
    for (int j = 0; j < 4; ++j) {
        const int c = c0 + ty + j * 8;
        const long long o = ((long long)b * 1024 + c) * 2048 + s0 + tx;
        vth[o] = __float2half_rn(tile[tx][ty + j * 8]);
    }
}

// --------------------- causal softmax -> fp16 ------------------------------
__global__ void softmax_causal_kernel(const float* __restrict__ att,
                                      __half* __restrict__ ph)
{
    const int row = blockIdx.x;
    const int b = row >> 11, t = row & 2047;
    const float* p = att + ((long long)b * 2048 + t) * 2048;
    __half* hrow = ph + ((long long)b * 2048 + t) * 2048;
    const int n = t + 1;
    const int zb = ((t >> 7) + 1) << 7;    // PV K-limit (128-aligned)
    const int tid = threadIdx.x;
    __shared__ float sbuf[8];

    float e[8];
    float m = -3.4e38f;
#pragma unroll
    for (int j = 0; j < 8; ++j) {
        const int i = tid + j * 256;
        e[j] = (i < n) ? p[i] : -3.4e38f;
        m = fmaxf(m, e[j]);
    }
#pragma unroll
    for (int o = 16; o > 0; o >>= 1) m = fmaxf(m, __shfl_xor_sync(0xffffffffu, m, o));
    if ((tid & 31) == 0) sbuf[tid >> 5] = m;
    __syncthreads();
    if (tid < 8) {
        float v = sbuf[tid];
#pragma unroll
        for (int o = 4; o > 0; o >>= 1) v = fmaxf(v, __shfl_xor_sync(0xffu, v, o));
        if (tid == 0) sbuf[0] = v;
    }
    __syncthreads();
    m = sbuf[0];
    __syncthreads();

    float s = 0.f;
#pragma unroll
    for (int j = 0; j < 8; ++j) {
        const int i = tid + j * 256;
        e[j] = (i < n) ? __expf(e[j] - m) : 0.f;
        s += e[j];
    }
#pragma unroll
    for (int o = 16; o > 0; o >>= 1) s += __shfl_xor_sync(0xffffffffu, s, o);
    if ((tid & 31) == 0) sbuf[tid >> 5] = s;
    __syncthreads();
    if (tid < 8) {
        float v = sbuf[tid];
#pragma unroll
        for (int o = 4; o > 0; o >>= 1) v += __shfl_xor_sync(0xffu, v, o);
        if (tid == 0) sbuf[0] = v;
    }
    __syncthreads();
    const float inv = 1.f / sbuf[0];

#pragma unroll
    for (int j = 0; j < 8; ++j) {
        const int i = tid + j * 256;
        if (i >= zb) break;
        hrow[i] = __float2half_rn(e[j] * inv);
    }
}

// ---------------------------------------------------------------------------
extern "C" void kernel_launch(void* const* d_in, const int* in_sizes, int n_in,
                              void* d_out, int out_size)
{
    const float* x = (const float*)d_in[0];
    const float* w = (const float*)d_in[1];
    float* out = (float*)d_out;

    float *att, *vf;
    __half *xh, *wh, *qh, *kh, *vth, *phb;
    cudaGetSymbolAddress((void**)&att, g_att);
    cudaGetSymbolAddress((void**)&vf, g_vf);
    cudaGetSymbolAddress((void**)&xh, g_xh);
    cudaGetSymbolAddress((void**)&wh, g_wh);
    cudaGetSymbolAddress((void**)&qh, g_qh);
    cudaGetSymbolAddress((void**)&kh, g_kh);
    cudaGetSymbolAddress((void**)&vth, g_vth);
    cudaGetSymbolAddress((void**)&phb, g_ph);

    cudaFuncSetAttribute(gemm1_kernel, cudaFuncAttributeMaxDynamicSharedMemorySize,
                         GEMM_SMEM);

    // 0) convert x and w to fp16
    {
        const long long total = X_N4 + W_N4;
        conv_xw_kernel<<<(int)((total + 255) / 256), 256>>>(x, w, xh, wh);
    }
    // 1) qkv = x @ w^T  (fused epilogue)
    {
        dim3 grid(3072 / 128, 8192 / 128, 1);
        gemm1_kernel<<<grid, 256, GEMM_SMEM>>>(xh, wh, nullptr,
                                               1024, 1024, 1024, 0,
                                               0, 0, 0, 1.0f, 0, 0, 1, 0);
    }
    // 2) transpose v -> fp16
    {
        dim3 grid(2048 / 32, 1024 / 32, 4);
        vtrans_kernel<<<grid, dim3(32, 8)>>>(vf, vth);
    }
    // 3) S = q k^T / 32  (causal tile skip)  [profiled slot]
    {
        dim3 grid(2048 / 128, 2048 / 128, 4);
        gemm1_kernel<<<grid, 256, GEMM_SMEM>>>(qh, kh, att,
                                               1024, 1024, 1024, 2048,
                                               2048LL * 1024, 2048LL * 1024, 2048LL * 2048,
                                               0.03125f, 1, 0, 0, 1);
    }
    // 4) P = softmax(S) -> fp16
    softmax_causal_kernel<<<4 * 2048, 256>>>(att, phb);

    // 5) y = P @ V  (V^T K-major, causal K-limit)
    {
        dim3 grid(1024 / 128, 2048 / 128, 4);
        gemm1_kernel<<<grid, 256, GEMM_SMEM>>>(phb, vth, out,
                                               2048, 2048, 2048, 1024,
                                               2048LL * 2048, 1024LL * 2048, 2048LL * 1024,
                                               1.0f, 0, 1, 0, 1);
    }
}

// round 16
// speedup vs baseline: 1.7901x; 1.1185x over previous
#include <cuda_runtime.h>
#include <cuda_fp16.h>
#include <cstdint>
#include <math.h>

// ---------------------------------------------------------------------------
// SingleHeadAttention B=4, T=2048, C=1024 fp32 — pure fp16 mma.sync GEMMs
//   qkv = x @ w^T   (fused epilogue -> q,k fp16, v fp32)
//   S   = q k^T/32  (causal tile-skip) -> att fp32
//   P   = softmax   -> fp16
//   y   = P @ (V^T)^T (causal K-limit)
// R16: CTA 128x256, 256 thr, 8 warps (2m x 4n) of 64x64, kc=64 (4 k16 steps),
//      3-stage cp.async, 1 CTA/SM, fragment set ping-pong across steps.
// ---------------------------------------------------------------------------

// ------------------------------ scratch ------------------------------------
__device__ float g_att[(size_t)4 * 2048 * 2048];
__device__ float g_vf[(size_t)4 * 2048 * 1024];
__device__ __half g_xh[(size_t)8192 * 1024];
__device__ __half g_wh[(size_t)3072 * 1024];
__device__ __half g_qh[(size_t)4 * 2048 * 1024];
__device__ __half g_kh[(size_t)4 * 2048 * 1024];
__device__ __half g_vth[(size_t)4 * 1024 * 2048];     // V^T
__device__ __half g_ph[(size_t)4 * 2048 * 2048];

// ------------------------------ helpers ------------------------------------
#define SA 72                                 // padded smem row stride (halfs), kc=64
#define TILE_A (128 * SA * 2)                 // 18432
#define TILE_BB (256 * SA * 2)                // 36864
#define STAGE_B (TILE_A + TILE_BB)            // 55296
#define GEMM_SMEM (3 * STAGE_B)               // 165888 (< 227KB)

__device__ __forceinline__ uint32_t smem_u32(const void* p) {
    uint32_t a;
    asm("{ .reg .u64 t; cvta.to.shared.u64 t, %1; cvt.u32.u64 %0, t; }" : "=r"(a) : "l"(p));
    return a;
}
__device__ __forceinline__ void cp16(uint32_t dst, const void* src) {
    asm volatile("cp.async.cg.shared.global [%0], [%1], 16;" :: "r"(dst), "l"(src));
}
__device__ __forceinline__ void ldmx4(uint32_t* r, uint32_t addr) {
    asm volatile("ldmatrix.sync.aligned.m8n8.x4.shared.b16 {%0,%1,%2,%3}, [%4];"
                 : "=r"(r[0]), "=r"(r[1]), "=r"(r[2]), "=r"(r[3]) : "r"(addr));
}
__device__ __forceinline__ void mma_f32(float* c, const uint32_t* a, const uint32_t* b) {
    asm volatile(
        "mma.sync.aligned.m16n8k16.row.col.f32.f16.f16.f32 "
        "{%0,%1,%2,%3}, {%4,%5,%6,%7}, {%8,%9}, {%0,%1,%2,%3};"
        : "+f"(c[0]), "+f"(c[1]), "+f"(c[2]), "+f"(c[3])
        : "r"(a[0]), "r"(a[1]), "r"(a[2]), "r"(a[3]), "r"(b[0]), "r"(b[1]));
}
__device__ __forceinline__ uint32_t pack2h(float v0, float v1) {
    __half2 h = __floats2half2_rn(v0, v1);
    return *(uint32_t*)&h;
}

// ------------------------------ GEMM ---------------------------------------
// mode 0: C = alpha * acc (fp32);  mode 1: fused qkv epilogue (q,k fp16, v f32)
__global__ __launch_bounds__(256, 1)
void gemm1_kernel(const __half* __restrict__ Ah, const __half* __restrict__ Bh,
                  float* __restrict__ C,
                  int K, int lda, int ldb, int ldc,
                  long long sAo, long long sBo, long long sCo,
                  float alpha, int causal_skip, int causal_klim, int mode, int rev_y)
{
    const int by = rev_y ? (gridDim.y - 1 - blockIdx.y) : blockIdx.y;
    const int m0 = by * 128;
    const int n0 = blockIdx.x * 256;
    if (causal_skip && n0 > m0 + 127) return;

    const int bz = blockIdx.z;
    Ah += (long long)bz * sAo;
    Bh += (long long)bz * sBo;
    C  += (long long)bz * sCo;

    int Keff = K;
    if (causal_klim) { int lim = m0 + 128; Keff = (lim < K) ? lim : K; }
    const int NC = Keff / 64;                  // kc = 64; NC >= 2 for all callers

    extern __shared__ char smem[];
    const uint32_t sb = smem_u32(smem);
    const int tid = threadIdx.x;
    const int wid = tid >> 5;
    const int lane = tid & 31;

    // stage loader: A 128r x 64k, B 256r x 64k; 8 x 16B chunks per row
    auto load_stage = [&](int s, int c) {
        const uint32_t base = sb + s * STAGE_B;
        const int k0 = c * 64;
#pragma unroll
        for (int it = 0; it < 4; ++it) {       // A: 1024 ids
            const int id  = tid + it * 256;
            const int row = id >> 3;
            const int c16 = id & 7;
            const uint32_t so = (uint32_t)(row * SA + c16 * 8) * 2;
            cp16(base + so, Ah + (long long)(m0 + row) * lda + k0 + c16 * 8);
        }
#pragma unroll
        for (int it = 0; it < 8; ++it) {       // B: 2048 ids
            const int id  = tid + it * 256;
            const int row = id >> 3;
            const int c16 = id & 7;
            const uint32_t so = (uint32_t)(row * SA + c16 * 8) * 2;
            cp16(base + TILE_A + so, Bh + (long long)(n0 + row) * ldb + k0 + c16 * 8);
        }
        asm volatile("cp.async.commit_group;" ::: "memory");
    };

    float acc[4][8][4];
#pragma unroll
    for (int i = 0; i < 4; ++i)
#pragma unroll
        for (int j = 0; j < 8; ++j)
#pragma unroll
            for (int q = 0; q < 4; ++q) acc[i][j][q] = 0.f;

    const int wm = (wid & 1) * 64;             // warp m offset (0/64)
    const int wn = (wid >> 1) * 64;            // warp n offset (0..192)
    const int gr = lane >> 3;
    const int rr = lane & 7;

    const uint32_t a_off = (uint32_t)((wm + (gr & 1) * 8 + rr) * SA + (gr >> 1) * 8) * 2;
    const uint32_t b_off = (uint32_t)((wn + (gr >> 1) * 8 + rr) * SA + (gr & 1) * 8) * 2;

    uint32_t fa0[4][4], fb0[8][2];
    uint32_t fa1[4][4], fb1[8][2];

    auto load_frags = [&](uint32_t st, uint32_t koff,
                          uint32_t (&fa)[4][4], uint32_t (&fb)[8][2]) {
#pragma unroll
        for (int nt = 0; nt < 4; ++nt) {
            uint32_t r[4];
            ldmx4(r, st + TILE_A + b_off + koff + (uint32_t)(nt * 16 * SA) * 2);
            fb[nt * 2 + 0][0] = r[0]; fb[nt * 2 + 0][1] = r[1];
            fb[nt * 2 + 1][0] = r[2]; fb[nt * 2 + 1][1] = r[3];
        }
#pragma unroll
        for (int mi = 0; mi < 4; ++mi)
            ldmx4(fa[mi], st + a_off + koff + (uint32_t)(mi * 16 * SA) * 2);
    };
    auto mma_all = [&](uint32_t (&fa)[4][4], uint32_t (&fb)[8][2]) {
#pragma unroll
        for (int mi = 0; mi < 4; ++mi)
#pragma unroll
            for (int nj = 0; nj < 8; ++nj) mma_f32(acc[mi][nj], fa[mi], fb[nj]);
    };

    // prologue: 3 stages in flight; frags for (chunk0, step0)
    load_stage(0, 0);
    load_stage(1, 1);
    load_stage(2, 2);
    asm volatile("cp.async.wait_group 2;" ::: "memory");
    __syncthreads();
    load_frags(sb, 0, fa0, fb0);

    for (int c = 0; c < NC; ++c) {
        const uint32_t st = sb + (c % 3) * STAGE_B;

        // steps 0..2: ping-pong frag sets within the chunk (k16 steps @32B)
        load_frags(st, 32, fa1, fb1);  mma_all(fa0, fb0);
        load_frags(st, 64, fa0, fb0);  mma_all(fa1, fb1);
        load_frags(st, 96, fa1, fb1);  mma_all(fa0, fb0);

        // boundary: stage c fully read; stage c+1 visible after barrier
        if (c + 2 < NC) asm volatile("cp.async.wait_group 1;" ::: "memory");
        else            asm volatile("cp.async.wait_group 0;" ::: "memory");
        __syncthreads();
        if (c + 3 < NC) load_stage(c % 3, c + 3);
        if (c + 1 < NC)
            load_frags(sb + ((c + 1) % 3) * STAGE_B, 0, fa0, fb0);

        // step 3
        mma_all(fa1, fb1);
    }

    // ---- epilogue ----
    if (mode == 0) {
#pragma unroll
        for (int mi = 0; mi < 4; ++mi)
#pragma unroll
            for (int nj = 0; nj < 8; ++nj) {
                const int row = m0 + wm + mi * 16 + (lane >> 2);
                const int col = n0 + wn + nj * 8 + (lane & 3) * 2;
                float2 v0 = make_float2(alpha * acc[mi][nj][0], alpha * acc[mi][nj][1]);
                float2 v1 = make_float2(alpha * acc[mi][nj][2], alpha * acc[mi][nj][3]);
                *(float2*)(C + (long long)row * ldc + col)       = v0;
                *(float2*)(C + (long long)(row + 8) * ldc + col) = v1;
            }
    } else {
        const int seg = n0 >> 10;                      // 0=q 1=k 2=v
        __half* dst = (seg == 0) ? g_qh : g_kh;
#pragma unroll
        for (int mi = 0; mi < 4; ++mi)
#pragma unroll
            for (int nj = 0; nj < 8; ++nj) {
                const int row = m0 + wm + mi * 16 + (lane >> 2);
                const int cc  = (n0 & 1023) + wn + nj * 8 + (lane & 3) * 2;
                const float v00 = acc[mi][nj][0], v01 = acc[mi][nj][1];
                const float v10 = acc[mi][nj][2], v11 = acc[mi][nj][3];
                const long long o0 = (long long)row * 1024 + cc;
                const long long o1 = (long long)(row + 8) * 1024 + cc;
                if (seg == 2) {
                    *(float2*)(g_vf + o0) = make_float2(v00, v01);
                    *(float2*)(g_vf + o1) = make_float2(v10, v11);
                } else {
                    *(uint32_t*)(dst + o0) = pack2h(v00, v01);
                    *(uint32_t*)(dst + o1) = pack2h(v10, v11);
                }
            }
    }
}

// --------------------- input convert (x, w -> fp16) ------------------------
#define X_N4 (8192LL * 1024 / 4)
#define W_N4 (3072LL * 1024 / 4)
__global__ void conv_xw_kernel(const float* __restrict__ x, const float* __restrict__ w,
                               __half* __restrict__ xh, __half* __restrict__ wh)
{
    long long i = (long long)blockIdx.x * blockDim.x + threadIdx.x;
    const float* src;
    __half* dst;
    long long o;
    if (i < X_N4) { src = x; dst = xh; o = i; }
    else {
        o = i - X_N4;
        if (o >= W_N4) return;
        src = w; dst = wh;
    }
    float4 v = *(const float4*)(src + o * 4);
    __half hv[4];
#pragma unroll
    for (int q = 0; q < 4; ++q) hv[q] = __float2half_rn((&v.x)[q]);
    *(uint2*)(dst + o * 4) = *(uint2*)hv;
}

// V transpose (fp32 -> fp16): vT[b][c][s] = vf[b*2048+s][c]
__global__ void vtrans_kernel(const float* __restrict__ vf, __half* __restrict__ vth)
{
    __shared__ float tile[32][33];
    const int s0 = blockIdx.x * 32, c0 = blockIdx.y * 32, b = blockIdx.z;
    const int tx = threadIdx.x, ty = threadIdx.y;
#pragma unroll
    for (int j = 0; j < 4; ++j) {
        const int s = s0 + ty + j * 8;
        tile[ty + j * 8][tx] = vf[(long long)(b * 2048 + s) * 1024 + c0 + tx];
    }
    __syncthreads();
#pragma unroll
    for (int j = 0; j < 4; ++j) {
        const int c = c0 + ty + j * 8;
        const long long o = ((long long)b * 1024 + c) * 2048 + s0 + tx;
        vth[o] = __float2half_rn(tile[tx][ty + j * 8]);
    }
}

// --------------------- causal softmax -> fp16 ------------------------------
__global__ void softmax_causal_kernel(const float* __restrict__ att,
                                      __half* __restrict__ ph)
{
    const int row = blockIdx.x;
    const int b = row >> 11, t = row & 2047;
    const float* p = att + ((long long)b * 2048 + t) * 2048;
    __half* hrow = ph + ((long long)b * 2048 + t) * 2048;
    const int n = t + 1;
    const int zb = ((t >> 7) + 1) << 7;    // PV K-limit (128-aligned)
    const int tid = threadIdx.x;
    __shared__ float sbuf[8];

    float e[8];
    float m = -3.4e38f;
#pragma unroll
    for (int j = 0; j < 8; ++j) {
        const int i = tid + j * 256;
        e[j] = (i < n) ? p[i] : -3.4e38f;
        m = fmaxf(m, e[j]);
    }
#pragma unroll
    for (int o = 16; o > 0; o >>= 1) m = fmaxf(m, __shfl_xor_sync(0xffffffffu, m, o));
    if ((tid & 31) == 0) sbuf[tid >> 5] = m;
    __syncthreads();
    if (tid < 8) {
        float v = sbuf[tid];
#pragma unroll
        for (int o = 4; o > 0; o >>= 1) v = fmaxf(v, __shfl_xor_sync(0xffu, v, o));
        if (tid == 0) sbuf[0] = v;
    }
    __syncthreads();
    m = sbuf[0];
    __syncthreads();

    float s = 0.f;
#pragma unroll
    for (int j = 0; j < 8; ++j) {
        const int i = tid + j * 256;
        e[j] = (i < n) ? __expf(e[j] - m) : 0.f;
        s += e[j];
    }
#pragma unroll
    for (int o = 16; o > 0; o >>= 1) s += __shfl_xor_sync(0xffffffffu, s, o);
    if ((tid & 31) == 0) sbuf[tid >> 5] = s;
    __syncthreads();
    if (tid < 8) {
        float v = sbuf[tid];
#pragma unroll
        for (int o = 4; o > 0; o >>= 1) v += __shfl_xor_sync(0xffu, v, o);
        if (tid == 0) sbuf[0] = v;
    }
    __syncthreads();
    const float inv = 1.f / sbuf[0];

#pragma unroll
    for (int j = 0; j < 8; ++j) {
        const int i = tid + j * 256;
        if (i >= zb) break;
        hrow[i] = __float2half_rn(e[j] * inv);
    }
}

// ---------------------------------------------------------------------------
extern "C" void kernel_launch(void* const* d_in, const int* in_sizes, int n_in,
                              void* d_out, int out_size)
{
    const float* x = (const float*)d_in[0];
    const float* w = (const float*)d_in[1];
    float* out = (float*)d_out;

    float *att, *vf;
    __half *xh, *wh, *qh, *kh, *vth, *phb;
    cudaGetSymbolAddress((void**)&att, g_att);
    cudaGetSymbolAddress((void**)&vf, g_vf);
    cudaGetSymbolAddress((void**)&xh, g_xh);
    cudaGetSymbolAddress((void**)&wh, g_wh);
    cudaGetSymbolAddress((void**)&qh, g_qh);
    cudaGetSymbolAddress((void**)&kh, g_kh);
    cudaGetSymbolAddress((void**)&vth, g_vth);
    cudaGetSymbolAddress((void**)&phb, g_ph);

    cudaFuncSetAttribute(gemm1_kernel, cudaFuncAttributeMaxDynamicSharedMemorySize,
                         GEMM_SMEM);

    // 0) convert x and w to fp16
    {
        const long long total = X_N4 + W_N4;
        conv_xw_kernel<<<(int)((total + 255) / 256), 256>>>(x, w, xh, wh);
    }
    // 1) qkv = x @ w^T  (fused epilogue)
    {
        dim3 grid(3072 / 256, 8192 / 128, 1);
        gemm1_kernel<<<grid, 256, GEMM_SMEM>>>(xh, wh, nullptr,
                                               1024, 1024, 1024, 0,
                                               0, 0, 0, 1.0f, 0, 0, 1, 0);
    }
    // 2) transpose v -> fp16
    {
        dim3 grid(2048 / 32, 1024 / 32, 4);
        vtrans_kernel<<<grid, dim3(32, 8)>>>(vf, vth);
    }
    // 3) S = q k^T / 32  (causal tile skip)  [profiled slot]
    {
        dim3 grid(2048 / 256, 2048 / 128, 4);
        gemm1_kernel<<<grid, 256, GEMM_SMEM>>>(qh, kh, att,
                                               1024, 1024, 1024, 2048,
                                               2048LL * 1024, 2048LL * 1024, 2048LL * 2048,
                                               0.03125f, 1, 0, 0, 1);
    }
    // 4) P = softmax(S) -> fp16
    softmax_causal_kernel<<<4 * 2048, 256>>>(att, phb);

    // 5) y = P @ V  (V^T K-major, causal K-limit)
    {
        dim3 grid(1024 / 256, 2048 / 128, 4);
        gemm1_kernel<<<grid, 256, GEMM_SMEM>>>(phb, vth, out,
                                               2048, 2048, 2048, 1024,
                                               2048LL * 2048, 1024LL * 2048, 2048LL * 1024,
                                               1.0f, 0, 1, 0, 1);
    }
}